// round 6
// baseline (speedup 1.0000x reference)
#include <cuda_runtime.h>

// PureCascadedBitFFN: out[elem, j] = j-th bit (LSB=0) of
// k = ceil(distance[elem] - 0.5) (exact reduction of the sigmoid cascade).
//
// 128 MB f32 output, never re-read. Steady-state limiter is the L2
// write-allocate + dirty-victim-evict round trip (R3-R5 all pinned at
// ~23us with no pipe saturated). This round: __stwt write-through stores -
// full 128B coalesced lines bypass L2 allocation entirely, so no victim
// evictions contend on the LTS.
//
// Grid/store mapping = best-known R3 layout: 4096 blocks x 2048-quad tiles,
// 256 threads x 8 coalesced 512B STG bursts. Shapes fixed, no bounds checks.

__global__ __launch_bounds__(256) void cascaded_bits_kernel(
    const float* __restrict__ dist,
    float4* __restrict__ out)
{
    const int base = blockIdx.x * 2048 + threadIdx.x;

    float r[8];
    #pragma unroll
    for (int i = 0; i < 8; i++)
        r[i] = __ldg(&dist[(base + i * 256) >> 2]);

    int k[8];
    #pragma unroll
    for (int i = 0; i < 8; i++)
        k[i] = __float2int_ru(r[i] - 0.5f);   // exact round-half-down

    #pragma unroll
    for (int i = 0; i < 8; i++) {
        const int q   = base + i * 256;
        const int bit = (q & 3) << 2;         // starting bit: 0,4,8,12
        float4 v;
        v.x = (float)((k[i] >> (bit + 0)) & 1);
        v.y = (float)((k[i] >> (bit + 1)) & 1);
        v.z = (float)((k[i] >> (bit + 2)) & 1);
        v.w = (float)((k[i] >> (bit + 3)) & 1);
        __stwt(&out[q], v);                   // write-through: no L2 allocate
    }
}

extern "C" void kernel_launch(void* const* d_in, const int* in_sizes, int n_in,
                              void* d_out, int out_size)
{
    const float* dist = (const float*)d_in[0];
    float4* out = (float4*)d_out;

    int n_elems = in_sizes[0];            // 512*4096 = 2,097,152
    int nquads  = n_elems * 4;            // 8,388,608
    int blocks  = nquads / 2048;          // 4096 (exact)

    cascaded_bits_kernel<<<blocks, 256>>>(dist, out);
}

// round 7
// speedup vs baseline: 1.1722x; 1.1722x over previous
#include <cuda_runtime.h>

// PureCascadedBitFFN: out[elem, j] = j-th bit (LSB=0) of
// k = ceil(distance[elem] - 0.5) (exact reduction of the 16-step sigmoid
// cascade in the reference).
//
// 128 MB f32 output, never re-read: pinned at the GB300 steady-state
// streaming-write wall (~5.9 TB/s; LTS cap ~6300 B/cyc is path-independent,
// so TMA/WT/persistent variants are all neutral or worse - verified R4-R6).
//
// Best-known layout (R3): 4096 blocks x 2048-quad tiles, 256 threads x 8
// coalesced 512B STG.128 bursts, __stcs evict-first (L2 still buffers and
// burst-forms the DRAM drain; write-through regressed).
//
// Micro-trim: bits are materialized as floats by integer select of
// 0x3F800000 (1.0f) instead of I2F - pure LOP/SHF, no convert-pipe latency
// in the store-feeding chain.

__global__ __launch_bounds__(256) void cascaded_bits_kernel(
    const float* __restrict__ dist,
    float4* __restrict__ out)
{
    const int base = blockIdx.x * 2048 + threadIdx.x;

    float r[8];
    #pragma unroll
    for (int i = 0; i < 8; i++)
        r[i] = __ldg(&dist[(base + i * 256) >> 2]);

    int k[8];
    #pragma unroll
    for (int i = 0; i < 8; i++)
        k[i] = __float2int_ru(r[i] - 0.5f);   // exact round-half-down

    #pragma unroll
    for (int i = 0; i < 8; i++) {
        const int q   = base + i * 256;
        const int bit = (q & 3) << 2;         // starting bit: 0,4,8,12
        // ((k>>b)&1) ? 1.0f : 0.0f  via integer mask of 0x3F800000
        float4 v;
        v.x = __int_as_float(((k[i] >> (bit + 0)) & 1) * 0x3F800000);
        v.y = __int_as_float(((k[i] >> (bit + 1)) & 1) * 0x3F800000);
        v.z = __int_as_float(((k[i] >> (bit + 2)) & 1) * 0x3F800000);
        v.w = __int_as_float(((k[i] >> (bit + 3)) & 1) * 0x3F800000);
        __stcs(&out[q], v);                   // streaming: evict-first in L2
    }
}

extern "C" void kernel_launch(void* const* d_in, const int* in_sizes, int n_in,
                              void* d_out, int out_size)
{
    const float* dist = (const float*)d_in[0];
    float4* out = (float4*)d_out;

    int n_elems = in_sizes[0];            // 512*4096 = 2,097,152
    int nquads  = n_elems * 4;            // 8,388,608
    int blocks  = nquads / 2048;          // 4096 (exact)

    cascaded_bits_kernel<<<blocks, 256>>>(dist, out);
}